// round 9
// baseline (speedup 1.0000x reference)
#include <cuda_runtime.h>
#include <cstdint>

#define NN 1000000
#define EE 1000000
#define CC 64
#define ROW 65           // C+1 floats per poss_edge row
#define ROWB 260         // row stride in bytes
#define GRID 740         // 5 blocks/SM * 148 SMs -> single wave
#define NODE_B 80
#define SCALAR_B 200
#define GROUPS (EE / 4)  // 250000 groups of 4 edges
#define WCHUNK 16        // groups per warp-steal
#define NCHUNKW ((GROUPS + WCHUNK - 1) / WCHUNK)

// Per-block partials: [block][0..5] = logp, maskN, sq, intr, raw, S
__device__ double g_part[GRID][6];
__device__ int g_counter;  // warp work-steal counter (reset by last block)
__device__ int g_done;     // arrival counter         (reset by last block)

__global__ void __launch_bounds__(256, 5) k_main(
    const float* __restrict__ pn,
    const float* __restrict__ pe,
    const int* __restrict__ gt,
    const uint8_t* __restrict__ mask,
    const int* __restrict__ edges,
    float* __restrict__ out)
{
    const int bid = blockIdx.x;
    const int lane = threadIdx.x & 31;
    const int wib = threadIdx.x >> 5;
    const int2* __restrict__ edges2 = (const int2*)edges;
    const int4* __restrict__ edges4 = (const int4*)edges;
    const char* __restrict__ peb = (const char*)pe;

    float f_logp = 0.0f, f_intr = 0.0f, f_raw = 0.0f, f_sq = 0.0f;
    int i_mask = 0, i_S = 0;

    if (bid < NODE_B) {
        // ---- node loss: ILP-4 thread-per-node ----
        const int ltid = bid * 256 + threadIdx.x;
        const int lnth = NODE_B * 256;
        int i = ltid;
        for (; i + 3 * lnth < NN; i += 4 * lnth) {
            int idx[4]; unsigned m[4]; int g[4];
            #pragma unroll
            for (int j = 0; j < 4; j++) idx[j] = i + j * lnth;
            #pragma unroll
            for (int j = 0; j < 4; j++) m[j] = mask[idx[j]];
            #pragma unroll
            for (int j = 0; j < 4; j++) g[j] = gt[idx[j]];
            float p[4];
            #pragma unroll
            for (int j = 0; j < 4; j++)
                p[j] = m[j] ? __ldcs(&pn[(size_t)idx[j] * CC + g[j]]) : 1.0f;
            #pragma unroll
            for (int j = 0; j < 4; j++)
                if (m[j]) { f_logp += __logf(p[j]); i_mask++; }
        }
        for (; i < NN; i += lnth) {
            if (mask[i]) {
                f_logp += __logf(__ldcs(&pn[(size_t)i * CC + gt[i]]));
                i_mask++;
            }
        }
    } else if (bid < NODE_B + SCALAR_B) {
        // ---- per-edge scalar terms: ILP-4 thread-per-edge ----
        const int ltid = (bid - NODE_B) * 256 + threadIdx.x;
        const int lnth = SCALAR_B * 256;
        int e = ltid;
        for (; e + 3 * lnth < EE; e += 4 * lnth) {
            int ei[4]; int2 ev[4]; float pl[4];
            unsigned m0[4], m1[4]; int g0[4], g1[4];
            #pragma unroll
            for (int j = 0; j < 4; j++) ei[j] = e + j * lnth;
            #pragma unroll
            for (int j = 0; j < 4; j++) ev[j] = edges2[ei[j]];
            #pragma unroll
            for (int j = 0; j < 4; j++) pl[j] = pe[(size_t)ei[j] * ROW + CC];
            #pragma unroll
            for (int j = 0; j < 4; j++) { m0[j] = mask[ev[j].x]; m1[j] = mask[ev[j].y]; }
            #pragma unroll
            for (int j = 0; j < 4; j++) { g0[j] = gt[ev[j].x]; g1[j] = gt[ev[j].y]; }
            #pragma unroll
            for (int j = 0; j < 4; j++) {
                f_intr += pl[j];
                if (m0[j] | m1[j]) {
                    i_S++;
                    float c;
                    if (m0[j] & m1[j]) {
                        c = (g0[j] == g1[j])
                              ? __logf(pe[(size_t)ei[j] * ROW + g0[j]])
                              : __logf(pl[j]);
                    } else {
                        int g = m0[j] ? g0[j] : g1[j];
                        c = __logf(pl[j] + pe[(size_t)ei[j] * ROW + g]);
                    }
                    f_raw -= c;
                }
            }
        }
        for (; e < EE; e += lnth) {
            int2 ev = edges2[e];
            float pl = pe[(size_t)e * ROW + CC];
            f_intr += pl;
            unsigned m0 = mask[ev.x], m1 = mask[ev.y];
            if (m0 | m1) {
                i_S++;
                float c;
                if (m0 & m1) {
                    int ga = gt[ev.x], gb = gt[ev.y];
                    c = (ga == gb) ? __logf(pe[(size_t)e * ROW + ga]) : __logf(pl);
                } else {
                    int g = m0 ? gt[ev.x] : gt[ev.y];
                    c = __logf(pl + pe[(size_t)e * ROW + g]);
                }
                f_raw -= c;
            }
        }
    }

    // ---- sqdiff: warp-per-4-edges, WARP-level work stealing (no barriers),
    //      pipelined int4 edge prefetch ----
    for (;;) {
        int c;
        if (lane == 0) c = atomicAdd(&g_counter, 1);
        c = __shfl_sync(0xffffffffu, c, 0);
        if (c >= NCHUNKW) break;
        const int gbeg = c * WCHUNK;
        const int gend = (gbeg + WCHUNK < GROUPS) ? gbeg + WCHUNK : GROUPS;

        // prologue: prefetch first group's edges (2 aligned 16B loads)
        int4 ep0 = __ldg(&edges4[gbeg * 2]);
        int4 ep1 = __ldg(&edges4[gbeg * 2 + 1]);

        for (int g = gbeg; g < gend; g++) {
            // 32-bit byte offsets into the row table
            unsigned oa[4], ob[4];
            oa[0] = (unsigned)ep0.x * ROWB;  ob[0] = (unsigned)ep0.y * ROWB;
            oa[1] = (unsigned)ep0.z * ROWB;  ob[1] = (unsigned)ep0.w * ROWB;
            oa[2] = (unsigned)ep1.x * ROWB;  ob[2] = (unsigned)ep1.y * ROWB;
            oa[3] = (unsigned)ep1.z * ROWB;  ob[3] = (unsigned)ep1.w * ROWB;

            // issue all 16 gather loads before consuming any
            float va[4], wa[4], vb[4], wb[4];
            #pragma unroll
            for (int j = 0; j < 4; j++) {
                const float* ra = (const float*)(peb + oa[j]);
                const float* rb = (const float*)(peb + ob[j]);
                va[j] = ra[lane];
                wa[j] = ra[lane + 32];
                vb[j] = rb[lane];
                wb[j] = rb[lane + 32];
            }
            // col-64 residual: lane j handles edge j
            float ca = 0.0f, cb = 0.0f;
            if (lane < 4) {
                ca = *(const float*)(peb + oa[lane] + CC * 4);
                cb = *(const float*)(peb + ob[lane] + CC * 4);
            }

            // prefetch NEXT group's edges while the 18 loads above are in flight
            if (g + 1 < gend) {
                ep0 = __ldg(&edges4[(g + 1) * 2]);
                ep1 = __ldg(&edges4[(g + 1) * 2 + 1]);
            }

            float s = 0.0f;
            #pragma unroll
            for (int j = 0; j < 4; j++) {
                float d0 = va[j] - vb[j];
                float d1 = wa[j] - wb[j];
                s += d0 * d0 + d1 * d1;
            }
            if (lane < 4) {
                float d2 = ca - cb;
                s += d2 * d2;
            }
            f_sq += s;
        }
    }

    // ---- block reduction -> per-block partial slot (no atomics) ----
    double vals[6] = {(double)f_logp, (double)i_mask, (double)f_sq,
                      (double)f_intr, (double)f_raw,  (double)i_S};
    #pragma unroll
    for (int k = 0; k < 6; k++) {
        double v = vals[k];
        #pragma unroll
        for (int o = 16; o; o >>= 1) v += __shfl_xor_sync(0xffffffffu, v, o);
        vals[k] = v;
    }
    __shared__ double sh[8][6];
    if (lane == 0) {
        #pragma unroll
        for (int k = 0; k < 6; k++) sh[wib][k] = vals[k];
    }
    __syncthreads();
    if (threadIdx.x < 6) {
        double t = 0.0;
        #pragma unroll
        for (int w = 0; w < 8; w++) t += sh[w][threadIdx.x];
        g_part[bid][threadIdx.x] = t;
    }

    // ---- last-block finalize (threadFenceReduction pattern) ----
    __threadfence();
    __syncthreads();
    __shared__ bool s_last;
    if (threadIdx.x == 0) {
        int prev = atomicAdd(&g_done, 1);
        s_last = (prev == GRID - 1);
    }
    __syncthreads();
    if (!s_last) return;

    __threadfence();  // order: see all g_part writes from other blocks
    if (threadIdx.x == 0) {
        g_done = 0;      // reset for next graph replay -- all blocks have
        g_counter = 0;   // finished stealing, so this cannot race
    }

    // warp k (k<6) reduces accumulator k over all blocks
    const int k = wib;
    __shared__ double acc[6];
    if (k < 6) {
        double t = 0.0;
        for (int b = lane; b < GRID; b += 32) t += g_part[b][k];
        #pragma unroll
        for (int o = 16; o; o >>= 1) t += __shfl_xor_sync(0xffffffffu, t, o);
        if (lane == 0) acc[k] = t;
    }
    __syncthreads();
    if (threadIdx.x == 0) {
        double loss = -acc[0] / acc[1];
        double semi = 0.5 * ((double)EE - acc[3]) * acc[2];   // SEMI_LAMBDA = 0.5
        double S    = acc[5];
        double edge = acc[4] / (S * S);                        // EDGE_LAMBDA^2 = 1
        out[0] = (float)(loss + semi + edge);
    }
}

extern "C" void kernel_launch(void* const* d_in, const int* in_sizes, int n_in,
                              void* d_out, int out_size) {
    const float*   pn    = (const float*)d_in[0];
    const float*   pe    = (const float*)d_in[1];
    const int*     gt    = (const int*)d_in[2];
    const uint8_t* mask  = (const uint8_t*)d_in[3];
    const int*     edges = (const int*)d_in[4];
    float* out = (float*)d_out;

    k_main<<<GRID, 256>>>(pn, pe, gt, mask, edges, out);
}

// round 10
// speedup vs baseline: 1.1717x; 1.1717x over previous
#include <cuda_runtime.h>
#include <cstdint>

#define NN 1000000
#define EE 1000000
#define CC 64
#define ROW 65           // C+1 floats per poss_edge row
#define ROWB 260         // row stride in bytes
#define GRID 592         // 4 blocks/SM * 148 SMs -> single wave
#define NODE_B 64
#define SCALAR_B 160
#define GROUPS (EE / 4)  // 250000 groups of 4 edges
#define WCHUNK 16        // groups per warp-steal
#define NCHUNKW ((GROUPS + WCHUNK - 1) / WCHUNK)

// Per-block partials: [block][0..5] = logp, maskN, sq, intr, raw, S
__device__ double g_part[GRID][6];
__device__ int g_counter;  // warp work-steal counter (reset by last block)
__device__ int g_done;     // arrival counter         (reset by last block)

__global__ void __launch_bounds__(256, 4) k_main(
    const float* __restrict__ pn,
    const float* __restrict__ pe,
    const int* __restrict__ gt,
    const uint8_t* __restrict__ mask,
    const int* __restrict__ edges,
    float* __restrict__ out)
{
    const int bid = blockIdx.x;
    const int lane = threadIdx.x & 31;
    const int wib = threadIdx.x >> 5;
    const int2* __restrict__ edges2 = (const int2*)edges;
    const int4* __restrict__ edges4 = (const int4*)edges;
    const char* __restrict__ peb = (const char*)pe;

    float f_logp = 0.0f, f_intr = 0.0f, f_raw = 0.0f, f_sq = 0.0f;
    int i_mask = 0, i_S = 0;

    if (bid < NODE_B) {
        // ---- node loss: ILP-4 thread-per-node ----
        const int ltid = bid * 256 + threadIdx.x;
        const int lnth = NODE_B * 256;
        int i = ltid;
        for (; i + 3 * lnth < NN; i += 4 * lnth) {
            int idx[4]; unsigned m[4]; int g[4];
            #pragma unroll
            for (int j = 0; j < 4; j++) idx[j] = i + j * lnth;
            #pragma unroll
            for (int j = 0; j < 4; j++) m[j] = mask[idx[j]];
            #pragma unroll
            for (int j = 0; j < 4; j++) g[j] = gt[idx[j]];
            float p[4];
            #pragma unroll
            for (int j = 0; j < 4; j++)
                p[j] = m[j] ? __ldcs(&pn[(size_t)idx[j] * CC + g[j]]) : 1.0f;
            #pragma unroll
            for (int j = 0; j < 4; j++)
                if (m[j]) { f_logp += __logf(p[j]); i_mask++; }
        }
        for (; i < NN; i += lnth) {
            if (mask[i]) {
                f_logp += __logf(__ldcs(&pn[(size_t)i * CC + gt[i]]));
                i_mask++;
            }
        }
    } else if (bid < NODE_B + SCALAR_B) {
        // ---- per-edge scalar terms: ILP-4 thread-per-edge ----
        const int ltid = (bid - NODE_B) * 256 + threadIdx.x;
        const int lnth = SCALAR_B * 256;
        int e = ltid;
        for (; e + 3 * lnth < EE; e += 4 * lnth) {
            int ei[4]; int2 ev[4]; float pl[4];
            unsigned m0[4], m1[4]; int g0[4], g1[4];
            #pragma unroll
            for (int j = 0; j < 4; j++) ei[j] = e + j * lnth;
            #pragma unroll
            for (int j = 0; j < 4; j++) ev[j] = edges2[ei[j]];
            #pragma unroll
            for (int j = 0; j < 4; j++) pl[j] = pe[(size_t)ei[j] * ROW + CC];
            #pragma unroll
            for (int j = 0; j < 4; j++) { m0[j] = mask[ev[j].x]; m1[j] = mask[ev[j].y]; }
            #pragma unroll
            for (int j = 0; j < 4; j++) { g0[j] = gt[ev[j].x]; g1[j] = gt[ev[j].y]; }
            #pragma unroll
            for (int j = 0; j < 4; j++) {
                f_intr += pl[j];
                if (m0[j] | m1[j]) {
                    i_S++;
                    float c;
                    if (m0[j] & m1[j]) {
                        c = (g0[j] == g1[j])
                              ? __logf(pe[(size_t)ei[j] * ROW + g0[j]])
                              : __logf(pl[j]);
                    } else {
                        int g = m0[j] ? g0[j] : g1[j];
                        c = __logf(pl[j] + pe[(size_t)ei[j] * ROW + g]);
                    }
                    f_raw -= c;
                }
            }
        }
        for (; e < EE; e += lnth) {
            int2 ev = edges2[e];
            float pl = pe[(size_t)e * ROW + CC];
            f_intr += pl;
            unsigned m0 = mask[ev.x], m1 = mask[ev.y];
            if (m0 | m1) {
                i_S++;
                float c;
                if (m0 & m1) {
                    int ga = gt[ev.x], gb = gt[ev.y];
                    c = (ga == gb) ? __logf(pe[(size_t)e * ROW + ga]) : __logf(pl);
                } else {
                    int g = m0 ? gt[ev.x] : gt[ev.y];
                    c = __logf(pl + pe[(size_t)e * ROW + g]);
                }
                f_raw -= c;
            }
        }
    }

    // ---- sqdiff: warp-per-4-edges, WARP-level work stealing (no barriers),
    //      pipelined int4 edge prefetch, 18-load register-resident batch ----
    for (;;) {
        int c;
        if (lane == 0) c = atomicAdd(&g_counter, 1);
        c = __shfl_sync(0xffffffffu, c, 0);
        if (c >= NCHUNKW) break;
        const int gbeg = c * WCHUNK;
        const int gend = (gbeg + WCHUNK < GROUPS) ? gbeg + WCHUNK : GROUPS;

        // prologue: prefetch first group's edges (2 aligned 16B loads)
        int4 ep0 = __ldg(&edges4[gbeg * 2]);
        int4 ep1 = __ldg(&edges4[gbeg * 2 + 1]);

        for (int g = gbeg; g < gend; g++) {
            // 32-bit byte offsets into the row table
            unsigned oa[4], ob[4];
            oa[0] = (unsigned)ep0.x * ROWB;  ob[0] = (unsigned)ep0.y * ROWB;
            oa[1] = (unsigned)ep0.z * ROWB;  ob[1] = (unsigned)ep0.w * ROWB;
            oa[2] = (unsigned)ep1.x * ROWB;  ob[2] = (unsigned)ep1.y * ROWB;
            oa[3] = (unsigned)ep1.z * ROWB;  ob[3] = (unsigned)ep1.w * ROWB;

            // issue all 16 gather loads before consuming any
            float va[4], wa[4], vb[4], wb[4];
            #pragma unroll
            for (int j = 0; j < 4; j++) {
                const float* ra = (const float*)(peb + oa[j]);
                const float* rb = (const float*)(peb + ob[j]);
                va[j] = ra[lane];
                wa[j] = ra[lane + 32];
                vb[j] = rb[lane];
                wb[j] = rb[lane + 32];
            }
            // col-64 residual: lane j handles edge j
            float ca = 0.0f, cb = 0.0f;
            if (lane < 4) {
                ca = *(const float*)(peb + oa[lane] + CC * 4);
                cb = *(const float*)(peb + ob[lane] + CC * 4);
            }

            // prefetch NEXT group's edges while the 18 loads above are in flight
            if (g + 1 < gend) {
                ep0 = __ldg(&edges4[(g + 1) * 2]);
                ep1 = __ldg(&edges4[(g + 1) * 2 + 1]);
            }

            float s = 0.0f;
            #pragma unroll
            for (int j = 0; j < 4; j++) {
                float d0 = va[j] - vb[j];
                float d1 = wa[j] - wb[j];
                s += d0 * d0 + d1 * d1;
            }
            if (lane < 4) {
                float d2 = ca - cb;
                s += d2 * d2;
            }
            f_sq += s;
        }
    }

    // ---- block reduction -> per-block partial slot (no atomics) ----
    double vals[6] = {(double)f_logp, (double)i_mask, (double)f_sq,
                      (double)f_intr, (double)f_raw,  (double)i_S};
    #pragma unroll
    for (int k = 0; k < 6; k++) {
        double v = vals[k];
        #pragma unroll
        for (int o = 16; o; o >>= 1) v += __shfl_xor_sync(0xffffffffu, v, o);
        vals[k] = v;
    }
    __shared__ double sh[8][6];
    if (lane == 0) {
        #pragma unroll
        for (int k = 0; k < 6; k++) sh[wib][k] = vals[k];
    }
    __syncthreads();
    if (threadIdx.x < 6) {
        double t = 0.0;
        #pragma unroll
        for (int w = 0; w < 8; w++) t += sh[w][threadIdx.x];
        g_part[bid][threadIdx.x] = t;
    }

    // ---- last-block finalize (threadFenceReduction pattern) ----
    __threadfence();
    __syncthreads();
    __shared__ bool s_last;
    if (threadIdx.x == 0) {
        int prev = atomicAdd(&g_done, 1);
        s_last = (prev == GRID - 1);
    }
    __syncthreads();
    if (!s_last) return;

    __threadfence();  // order: see all g_part writes from other blocks
    if (threadIdx.x == 0) {
        g_done = 0;      // reset for next graph replay -- all blocks have
        g_counter = 0;   // finished stealing, so this cannot race
    }

    // warp k (k<6) reduces accumulator k over all blocks
    const int k = wib;
    __shared__ double acc[6];
    if (k < 6) {
        double t = 0.0;
        for (int b = lane; b < GRID; b += 32) t += g_part[b][k];
        #pragma unroll
        for (int o = 16; o; o >>= 1) t += __shfl_xor_sync(0xffffffffu, t, o);
        if (lane == 0) acc[k] = t;
    }
    __syncthreads();
    if (threadIdx.x == 0) {
        double loss = -acc[0] / acc[1];
        double semi = 0.5 * ((double)EE - acc[3]) * acc[2];   // SEMI_LAMBDA = 0.5
        double S    = acc[5];
        double edge = acc[4] / (S * S);                        // EDGE_LAMBDA^2 = 1
        out[0] = (float)(loss + semi + edge);
    }
}

extern "C" void kernel_launch(void* const* d_in, const int* in_sizes, int n_in,
                              void* d_out, int out_size) {
    const float*   pn    = (const float*)d_in[0];
    const float*   pe    = (const float*)d_in[1];
    const int*     gt    = (const int*)d_in[2];
    const uint8_t* mask  = (const uint8_t*)d_in[3];
    const int*     edges = (const int*)d_in[4];
    float* out = (float*)d_out;

    k_main<<<GRID, 256>>>(pn, pe, gt, mask, edges, out);
}

// round 12
// speedup vs baseline: 1.1720x; 1.0003x over previous
#include <cuda_runtime.h>
#include <cstdint>

#define NN 1000000
#define EE 1000000
#define CC 64
#define ROW 65           // C+1 floats per poss_edge row
#define ROWB 260         // row stride in bytes
#define GRID 592         // 4 blocks/SM * 148 SMs -> single wave
#define NODE_B 64
#define SCALAR_B 160
#define GROUPS (EE / 4)  // 250000 groups of 4 edges
#define WCHUNK 16        // groups per warp-steal
#define NCHUNKW ((GROUPS + WCHUNK - 1) / WCHUNK)

// Per-block partials: [block][0..5] = logp, maskN, sq, intr, raw, S
__device__ double g_part[GRID][6];
__device__ int g_counter;  // warp work-steal counter (reset by last block)
__device__ int g_done;     // arrival counter         (reset by last block)

// L2 evict_last access policy (scalar loads need createpolicy + cache_hint)
__device__ __forceinline__ uint64_t mk_policy_el() {
    uint64_t p;
    asm("createpolicy.fractional.L2::evict_last.b64 %0, 1.0;" : "=l"(p));
    return p;
}
__device__ __forceinline__ float ldg_el(const float* p, uint64_t pol) {
    float v;
    asm volatile("ld.global.nc.L2::cache_hint.f32 %0, [%1], %2;"
                 : "=f"(v) : "l"(p), "l"(pol));
    return v;
}

__global__ void __launch_bounds__(256, 4) k_main(
    const float* __restrict__ pn,
    const float* __restrict__ pe,
    const int* __restrict__ gt,
    const uint8_t* __restrict__ mask,
    const int* __restrict__ edges,
    float* __restrict__ out)
{
    const int bid = blockIdx.x;
    const int lane = threadIdx.x & 31;
    const int wib = threadIdx.x >> 5;
    const int2* __restrict__ edges2 = (const int2*)edges;
    const int4* __restrict__ edges4 = (const int4*)edges;
    const char* __restrict__ peb = (const char*)pe;

    float f_logp = 0.0f, f_intr = 0.0f, f_raw = 0.0f, f_sq = 0.0f;
    int i_mask = 0, i_S = 0;

    if (bid < NODE_B) {
        // ---- node loss: ILP-4 thread-per-node ----
        const int ltid = bid * 256 + threadIdx.x;
        const int lnth = NODE_B * 256;
        int i = ltid;
        for (; i + 3 * lnth < NN; i += 4 * lnth) {
            int idx[4]; unsigned m[4]; int g[4];
            #pragma unroll
            for (int j = 0; j < 4; j++) idx[j] = i + j * lnth;
            #pragma unroll
            for (int j = 0; j < 4; j++) m[j] = mask[idx[j]];
            #pragma unroll
            for (int j = 0; j < 4; j++) g[j] = gt[idx[j]];
            float p[4];
            #pragma unroll
            for (int j = 0; j < 4; j++)
                p[j] = m[j] ? __ldcs(&pn[(size_t)idx[j] * CC + g[j]]) : 1.0f;
            #pragma unroll
            for (int j = 0; j < 4; j++)
                if (m[j]) { f_logp += __logf(p[j]); i_mask++; }
        }
        for (; i < NN; i += lnth) {
            if (mask[i]) {
                f_logp += __logf(__ldcs(&pn[(size_t)i * CC + gt[i]]));
                i_mask++;
            }
        }
    } else if (bid < NODE_B + SCALAR_B) {
        // ---- per-edge scalar terms: ILP-4 thread-per-edge ----
        const int ltid = (bid - NODE_B) * 256 + threadIdx.x;
        const int lnth = SCALAR_B * 256;
        int e = ltid;
        for (; e + 3 * lnth < EE; e += 4 * lnth) {
            int ei[4]; int2 ev[4]; float pl[4];
            unsigned m0[4], m1[4]; int g0[4], g1[4];
            #pragma unroll
            for (int j = 0; j < 4; j++) ei[j] = e + j * lnth;
            #pragma unroll
            for (int j = 0; j < 4; j++) ev[j] = edges2[ei[j]];
            #pragma unroll
            for (int j = 0; j < 4; j++) pl[j] = __ldcs(&pe[(size_t)ei[j] * ROW + CC]);
            #pragma unroll
            for (int j = 0; j < 4; j++) { m0[j] = mask[ev[j].x]; m1[j] = mask[ev[j].y]; }
            #pragma unroll
            for (int j = 0; j < 4; j++) { g0[j] = gt[ev[j].x]; g1[j] = gt[ev[j].y]; }
            #pragma unroll
            for (int j = 0; j < 4; j++) {
                f_intr += pl[j];
                if (m0[j] | m1[j]) {
                    i_S++;
                    float c;
                    if (m0[j] & m1[j]) {
                        c = (g0[j] == g1[j])
                              ? __logf(__ldcs(&pe[(size_t)ei[j] * ROW + g0[j]]))
                              : __logf(pl[j]);
                    } else {
                        int g = m0[j] ? g0[j] : g1[j];
                        c = __logf(pl[j] + __ldcs(&pe[(size_t)ei[j] * ROW + g]));
                    }
                    f_raw -= c;
                }
            }
        }
        for (; e < EE; e += lnth) {
            int2 ev = edges2[e];
            float pl = __ldcs(&pe[(size_t)e * ROW + CC]);
            f_intr += pl;
            unsigned m0 = mask[ev.x], m1 = mask[ev.y];
            if (m0 | m1) {
                i_S++;
                float c;
                if (m0 & m1) {
                    int ga = gt[ev.x], gb = gt[ev.y];
                    c = (ga == gb) ? __logf(__ldcs(&pe[(size_t)e * ROW + ga])) : __logf(pl);
                } else {
                    int g = m0 ? gt[ev.x] : gt[ev.y];
                    c = __logf(pl + __ldcs(&pe[(size_t)e * ROW + g]));
                }
                f_raw -= c;
            }
        }
    }

    // ---- sqdiff: warp-per-4-edges, WARP-level work stealing (no barriers),
    //      pipelined int4 edge prefetch, evict_last row gathers ----
    const uint64_t pol = mk_policy_el();
    for (;;) {
        int c;
        if (lane == 0) c = atomicAdd(&g_counter, 1);
        c = __shfl_sync(0xffffffffu, c, 0);
        if (c >= NCHUNKW) break;
        const int gbeg = c * WCHUNK;
        const int gend = (gbeg + WCHUNK < GROUPS) ? gbeg + WCHUNK : GROUPS;

        // prologue: prefetch first group's edges (2 aligned 16B loads)
        int4 ep0 = __ldg(&edges4[gbeg * 2]);
        int4 ep1 = __ldg(&edges4[gbeg * 2 + 1]);

        for (int g = gbeg; g < gend; g++) {
            // 32-bit byte offsets into the row table
            unsigned oa[4], ob[4];
            oa[0] = (unsigned)ep0.x * ROWB;  ob[0] = (unsigned)ep0.y * ROWB;
            oa[1] = (unsigned)ep0.z * ROWB;  ob[1] = (unsigned)ep0.w * ROWB;
            oa[2] = (unsigned)ep1.x * ROWB;  ob[2] = (unsigned)ep1.y * ROWB;
            oa[3] = (unsigned)ep1.z * ROWB;  ob[3] = (unsigned)ep1.w * ROWB;

            // issue all 16 gather loads (L2 evict_last) before consuming any
            float va[4], wa[4], vb[4], wb[4];
            #pragma unroll
            for (int j = 0; j < 4; j++) {
                const float* ra = (const float*)(peb + oa[j]);
                const float* rb = (const float*)(peb + ob[j]);
                va[j] = ldg_el(ra + lane, pol);
                wa[j] = ldg_el(ra + lane + 32, pol);
                vb[j] = ldg_el(rb + lane, pol);
                wb[j] = ldg_el(rb + lane + 32, pol);
            }
            // col-64 residual: lane j handles edge j (same rows -> cache hits)
            float ca = 0.0f, cb = 0.0f;
            if (lane < 4) {
                ca = *(const float*)(peb + oa[lane] + CC * 4);
                cb = *(const float*)(peb + ob[lane] + CC * 4);
            }

            // prefetch NEXT group's edges while the 18 loads above are in flight
            if (g + 1 < gend) {
                ep0 = __ldg(&edges4[(g + 1) * 2]);
                ep1 = __ldg(&edges4[(g + 1) * 2 + 1]);
            }

            float s = 0.0f;
            #pragma unroll
            for (int j = 0; j < 4; j++) {
                float d0 = va[j] - vb[j];
                float d1 = wa[j] - wb[j];
                s += d0 * d0 + d1 * d1;
            }
            if (lane < 4) {
                float d2 = ca - cb;
                s += d2 * d2;
            }
            f_sq += s;
        }
    }

    // ---- block reduction -> per-block partial slot (no atomics) ----
    double vals[6] = {(double)f_logp, (double)i_mask, (double)f_sq,
                      (double)f_intr, (double)f_raw,  (double)i_S};
    #pragma unroll
    for (int k = 0; k < 6; k++) {
        double v = vals[k];
        #pragma unroll
        for (int o = 16; o; o >>= 1) v += __shfl_xor_sync(0xffffffffu, v, o);
        vals[k] = v;
    }
    __shared__ double sh[8][6];
    if (lane == 0) {
        #pragma unroll
        for (int k = 0; k < 6; k++) sh[wib][k] = vals[k];
    }
    __syncthreads();
    if (threadIdx.x < 6) {
        double t = 0.0;
        #pragma unroll
        for (int w = 0; w < 8; w++) t += sh[w][threadIdx.x];
        g_part[bid][threadIdx.x] = t;
    }

    // ---- last-block finalize (threadFenceReduction pattern) ----
    __threadfence();
    __syncthreads();
    __shared__ bool s_last;
    if (threadIdx.x == 0) {
        int prev = atomicAdd(&g_done, 1);
        s_last = (prev == GRID - 1);
    }
    __syncthreads();
    if (!s_last) return;

    __threadfence();  // order: see all g_part writes from other blocks
    if (threadIdx.x == 0) {
        g_done = 0;      // reset for next graph replay -- all blocks have
        g_counter = 0;   // finished stealing, so this cannot race
    }

    // warp k (k<6) reduces accumulator k over all blocks
    const int k = wib;
    __shared__ double acc[6];
    if (k < 6) {
        double t = 0.0;
        for (int b = lane; b < GRID; b += 32) t += g_part[b][k];
        #pragma unroll
        for (int o = 16; o; o >>= 1) t += __shfl_xor_sync(0xffffffffu, t, o);
        if (lane == 0) acc[k] = t;
    }
    __syncthreads();
    if (threadIdx.x == 0) {
        double loss = -acc[0] / acc[1];
        double semi = 0.5 * ((double)EE - acc[3]) * acc[2];   // SEMI_LAMBDA = 0.5
        double S    = acc[5];
        double edge = acc[4] / (S * S);                        // EDGE_LAMBDA^2 = 1
        out[0] = (float)(loss + semi + edge);
    }
}

extern "C" void kernel_launch(void* const* d_in, const int* in_sizes, int n_in,
                              void* d_out, int out_size) {
    const float*   pn    = (const float*)d_in[0];
    const float*   pe    = (const float*)d_in[1];
    const int*     gt    = (const int*)d_in[2];
    const uint8_t* mask  = (const uint8_t*)d_in[3];
    const int*     edges = (const int*)d_in[4];
    float* out = (float*)d_out;

    k_main<<<GRID, 256>>>(pn, pe, gt, mask, edges, out);
}